// round 1
// baseline (speedup 1.0000x reference)
#include <cuda_runtime.h>
#include <math.h>

#define NB   512
#define TT   32
#define DD   1024
#define HH   1024
#define FH   4096

// Scratch (allocation-free rule: __device__ globals)
__device__ float g_Xf[(size_t)NB * TT * FH];   // precomputed x@Wx + b  (256 MB)
__device__ float g_h[NB * HH];
__device__ float g_c[NB * HH];
__device__ float g_attn[NB * HH];
__device__ float g_v[NB * FH];

// ---------------------------------------------------------------------------
// init: h0 = c0 = mean over the 16 spatial values of A[n,h,:,:]
// ---------------------------------------------------------------------------
__global__ void init_hc(const float* __restrict__ A) {
    int idx = blockIdx.x * blockDim.x + threadIdx.x;
    if (idx >= NB * HH) return;
    const float4* p = (const float4*)(A + (size_t)idx * 16);
    float4 a = p[0], b = p[1], c = p[2], d = p[3];
    float s = (a.x + a.y + a.z + a.w) + (b.x + b.y + b.z + b.w)
            + (c.x + c.y + c.z + c.w) + (d.x + d.y + d.z + d.w);
    s *= (1.0f / 16.0f);
    g_h[idx] = s;
    g_c[idx] = s;
}

// ---------------------------------------------------------------------------
// Precompute GEMM: g_Xf[m, c] = sum_k x[m,k] * Wx[k,c] + b[c]
//   m over N*T = 16384, K = 1024, C = 4096.  128x128 tile, BK=16, 8x8/thread.
// ---------------------------------------------------------------------------
__global__ __launch_bounds__(256) void gemm_x(const float* __restrict__ A,
                                              const float* __restrict__ B,
                                              const float* __restrict__ bias) {
    __shared__ float As[16][128];
    __shared__ float Bs[16][128];
    int tid = threadIdx.x;
    int tx = tid & 15, ty = tid >> 4;
    int rowBase = blockIdx.y * 128;
    int colBase = blockIdx.x * 128;
    float acc[8][8] = {};

    for (int kt = 0; kt < DD; kt += 16) {
        {   // A tile: 128 rows x 16 k, transposed into smem
            int r  = tid >> 2;
            int kg = (tid & 3) * 4;
            #pragma unroll
            for (int rr = 0; rr < 2; rr++) {
                int row = r + rr * 64;
                float4 v = *(const float4*)(A + (size_t)(rowBase + row) * DD + kt + kg);
                As[kg + 0][row] = v.x; As[kg + 1][row] = v.y;
                As[kg + 2][row] = v.z; As[kg + 3][row] = v.w;
            }
        }
        {   // B tile: 16 k x 128 cols
            int kr = tid >> 5;
            int cg = (tid & 31) * 4;
            #pragma unroll
            for (int rr = 0; rr < 2; rr++) {
                int k = kr + rr * 8;
                *(float4*)&Bs[k][cg] =
                    *(const float4*)(B + (size_t)(kt + k) * FH + colBase + cg);
            }
        }
        __syncthreads();
        #pragma unroll
        for (int kk = 0; kk < 16; kk++) {
            float a[8], bb[8];
            #pragma unroll
            for (int i = 0; i < 8; i++) a[i]  = As[kk][ty * 8 + i];
            #pragma unroll
            for (int j = 0; j < 8; j++) bb[j] = Bs[kk][tx * 8 + j];
            #pragma unroll
            for (int i = 0; i < 8; i++)
                #pragma unroll
                for (int j = 0; j < 8; j++)
                    acc[i][j] += a[i] * bb[j];
        }
        __syncthreads();
    }

    #pragma unroll
    for (int i = 0; i < 8; i++) {
        int row = rowBase + ty * 8 + i;
        #pragma unroll
        for (int j = 0; j < 8; j += 4) {
            int col = colBase + tx * 8 + j;
            float4 v;
            v.x = acc[i][j + 0] + bias[col + 0];
            v.y = acc[i][j + 1] + bias[col + 1];
            v.z = acc[i][j + 2] + bias[col + 2];
            v.w = acc[i][j + 3] + bias[col + 3];
            *(float4*)(g_Xf + (size_t)row * FH + col) = v;
        }
    }
}

// ---------------------------------------------------------------------------
// Attention: one block per n.
//   scores[k] = sum_h h[n,h]*Af[n,h,k] / 32 ; M = softmax(scores)
//   attn[n,h] = sum_k Af[n,h,k]*M[k]
// ---------------------------------------------------------------------------
__global__ __launch_bounds__(256) void attention(const float* __restrict__ A) {
    int n = blockIdx.x;
    const float* Afn = A + (size_t)n * (HH * 16);
    const float* hn  = g_h + (size_t)n * HH;

    float acc[16];
    #pragma unroll
    for (int k = 0; k < 16; k++) acc[k] = 0.0f;

    for (int hh = threadIdx.x; hh < HH; hh += 256) {
        float hv = hn[hh];
        const float4* row = (const float4*)(Afn + (size_t)hh * 16);
        float4 r0 = row[0], r1 = row[1], r2 = row[2], r3 = row[3];
        acc[0]  += hv * r0.x; acc[1]  += hv * r0.y; acc[2]  += hv * r0.z; acc[3]  += hv * r0.w;
        acc[4]  += hv * r1.x; acc[5]  += hv * r1.y; acc[6]  += hv * r1.z; acc[7]  += hv * r1.w;
        acc[8]  += hv * r2.x; acc[9]  += hv * r2.y; acc[10] += hv * r2.z; acc[11] += hv * r2.w;
        acc[12] += hv * r3.x; acc[13] += hv * r3.y; acc[14] += hv * r3.z; acc[15] += hv * r3.w;
    }
    // warp reduce each of the 16 partials
    #pragma unroll
    for (int off = 16; off > 0; off >>= 1)
        #pragma unroll
        for (int k = 0; k < 16; k++)
            acc[k] += __shfl_xor_sync(0xffffffffu, acc[k], off);

    __shared__ float warpacc[8][16];
    __shared__ float Msm[16];
    int lane = threadIdx.x & 31, wid = threadIdx.x >> 5;
    if (lane == 0) {
        #pragma unroll
        for (int k = 0; k < 16; k++) warpacc[wid][k] = acc[k];
    }
    __syncthreads();
    if (threadIdx.x == 0) {
        float sc[16];
        #pragma unroll
        for (int k = 0; k < 16; k++) {
            float s = 0.0f;
            #pragma unroll
            for (int w = 0; w < 8; w++) s += warpacc[w][k];
            sc[k] = s * (1.0f / 32.0f);   // scale = sqrt(1024)
        }
        float mx = sc[0];
        #pragma unroll
        for (int k = 1; k < 16; k++) mx = fmaxf(mx, sc[k]);
        float sum = 0.0f;
        #pragma unroll
        for (int k = 0; k < 16; k++) { sc[k] = expf(sc[k] - mx); sum += sc[k]; }
        float inv = 1.0f / sum;
        #pragma unroll
        for (int k = 0; k < 16; k++) Msm[k] = sc[k] * inv;
    }
    __syncthreads();

    float m[16];
    #pragma unroll
    for (int k = 0; k < 16; k++) m[k] = Msm[k];
    for (int hh = threadIdx.x; hh < HH; hh += 256) {
        const float4* row = (const float4*)(Afn + (size_t)hh * 16);
        float4 r0 = row[0], r1 = row[1], r2 = row[2], r3 = row[3];
        float s = r0.x*m[0] + r0.y*m[1] + r0.z*m[2] + r0.w*m[3]
                + r1.x*m[4] + r1.y*m[5] + r1.z*m[6] + r1.w*m[7]
                + r2.x*m[8] + r2.y*m[9] + r2.z*m[10] + r2.w*m[11]
                + r3.x*m[12] + r3.y*m[13] + r3.z*m[14] + r3.w*m[15];
        g_attn[(size_t)n * HH + hh] = s;
    }
}

// ---------------------------------------------------------------------------
// Step GEMM: g_v = g_h @ Wh + g_attn @ Wattn + Xf[:, t, :]
//   M = 512, C = 4096, K = 2048 (concatenated). Same tiling as gemm_x.
// ---------------------------------------------------------------------------
__global__ __launch_bounds__(256) void gemm_step(const float* __restrict__ Wh,
                                                 const float* __restrict__ Wattn,
                                                 int t) {
    __shared__ float As[16][128];
    __shared__ float Bs[16][128];
    int tid = threadIdx.x;
    int tx = tid & 15, ty = tid >> 4;
    int rowBase = blockIdx.y * 128;
    int colBase = blockIdx.x * 128;
    float acc[8][8] = {};

    for (int kt = 0; kt < 2 * HH; kt += 16) {
        const float* Asrc = (kt < HH) ? g_h : g_attn;
        const float* Bsrc = (kt < HH) ? Wh  : Wattn;
        int kk0 = kt & (HH - 1);
        {
            int r  = tid >> 2;
            int kg = (tid & 3) * 4;
            #pragma unroll
            for (int rr = 0; rr < 2; rr++) {
                int row = r + rr * 64;
                float4 v = *(const float4*)(Asrc + (size_t)(rowBase + row) * HH + kk0 + kg);
                As[kg + 0][row] = v.x; As[kg + 1][row] = v.y;
                As[kg + 2][row] = v.z; As[kg + 3][row] = v.w;
            }
        }
        {
            int kr = tid >> 5;
            int cg = (tid & 31) * 4;
            #pragma unroll
            for (int rr = 0; rr < 2; rr++) {
                int k = kr + rr * 8;
                *(float4*)&Bs[k][cg] =
                    *(const float4*)(Bsrc + (size_t)(kk0 + k) * FH + colBase + cg);
            }
        }
        __syncthreads();
        #pragma unroll
        for (int kk = 0; kk < 16; kk++) {
            float a[8], bb[8];
            #pragma unroll
            for (int i = 0; i < 8; i++) a[i]  = As[kk][ty * 8 + i];
            #pragma unroll
            for (int j = 0; j < 8; j++) bb[j] = Bs[kk][tx * 8 + j];
            #pragma unroll
            for (int i = 0; i < 8; i++)
                #pragma unroll
                for (int j = 0; j < 8; j++)
                    acc[i][j] += a[i] * bb[j];
        }
        __syncthreads();
    }

    // epilogue: + Xf[n, t, :]  (Xf row stride = T*FH, offset t*FH)
    #pragma unroll
    for (int i = 0; i < 8; i++) {
        int row = rowBase + ty * 8 + i;
        const float* xf = g_Xf + (size_t)row * (TT * FH) + (size_t)t * FH;
        #pragma unroll
        for (int j = 0; j < 8; j += 4) {
            int col = colBase + tx * 8 + j;
            float4 xv = *(const float4*)(xf + col);
            float4 v;
            v.x = acc[i][j + 0] + xv.x;
            v.y = acc[i][j + 1] + xv.y;
            v.z = acc[i][j + 2] + xv.z;
            v.w = acc[i][j + 3] + xv.w;
            *(float4*)(g_v + (size_t)row * FH + col) = v;
        }
    }
}

// ---------------------------------------------------------------------------
// Gates: i,f,o,g -> update c,h ; write h to out[n, t, :]
// ---------------------------------------------------------------------------
__device__ __forceinline__ float sigmoidf_(float x) {
    return 1.0f / (1.0f + expf(-x));
}

__global__ void gates(float* __restrict__ out, int t) {
    int idx = blockIdx.x * blockDim.x + threadIdx.x;
    if (idx >= NB * HH) return;
    int n = idx >> 10;          // H = 1024
    int j = idx & 1023;
    const float* vn = g_v + (size_t)n * FH;
    float vi = sigmoidf_(vn[j]);
    float vf = sigmoidf_(vn[j + HH]);
    float vo = sigmoidf_(vn[j + 2 * HH]);
    float vg = tanhf(vn[j + 3 * HH]);
    float cc = vf * g_c[idx] + vi * vg;
    float hh = vo * tanhf(cc);
    g_c[idx] = cc;
    g_h[idx] = hh;
    out[((size_t)n * TT + t) * HH + j] = hh;
}

// ---------------------------------------------------------------------------
extern "C" void kernel_launch(void* const* d_in, const int* in_sizes, int n_in,
                              void* d_out, int out_size) {
    const float* x     = (const float*)d_in[0];
    const float* A     = (const float*)d_in[1];
    const float* Wx    = (const float*)d_in[2];
    const float* Wh    = (const float*)d_in[3];
    const float* Wattn = (const float*)d_in[4];
    const float* b     = (const float*)d_in[5];
    float* out = (float*)d_out;

    init_hc<<<(NB * HH) / 256, 256>>>(A);
    // Xf = x.reshape(N*T, D) @ Wx + b   (hoisted out of the recurrence)
    gemm_x<<<dim3(FH / 128, (NB * TT) / 128), 256>>>(x, Wx, b);

    for (int t = 0; t < TT; t++) {
        attention<<<NB, 256>>>(A);
        gemm_step<<<dim3(FH / 128, NB / 128), 256>>>(Wh, Wattn, t);
        gates<<<(NB * HH) / 256, 256>>>(out, t);
    }
}

// round 6
// speedup vs baseline: 2.6156x; 2.6156x over previous
#include <cuda_runtime.h>
#include <cuda_bf16.h>
#include <math.h>
#include <stdint.h>

#define NB   512
#define TT   32
#define DD   1024
#define HH   1024
#define FH   4096

typedef __nv_bfloat16 bf16;

// ---------------------------------------------------------------------------
// Scratch (__device__ globals; allocation-free rule)
// ---------------------------------------------------------------------------
__device__ float g_Xf[(size_t)NB * TT * FH];          // x@Wx + b, permuted cols (256 MB)
__device__ float g_h[NB * HH];                        // fp32 h (for attention)
__device__ float g_c[NB * HH];
// Double-buffered MMA A-operand [h | attn]
__device__ bf16  g_Ahi[2][NB * 2048];
__device__ bf16  g_Alo[2][NB * 2048];
__device__ bf16  g_xhi[(size_t)NB * TT * DD];
__device__ bf16  g_xlo[(size_t)NB * TT * DD];
__device__ bf16  g_WsThi[(size_t)FH * 2048];          // [Wh;Wattn]^T, permuted rows
__device__ bf16  g_WsTlo[(size_t)FH * 2048];
__device__ bf16  g_WxThi[(size_t)FH * DD];            // Wx^T, permuted rows
__device__ bf16  g_WxTlo[(size_t)FH * DD];
__device__ float g_bperm[FH];

// Column permutation: orig col n = gate*1024 + j  ->  p = (j/32)*128 + gate*32 + j%32
__device__ __forceinline__ int perm(int n) {
    int gate = n >> 10, j = n & 1023;
    return ((j >> 5) << 7) + (gate << 5) + (j & 31);
}

// ---------------------------------------------------------------------------
// PTX helpers
// ---------------------------------------------------------------------------
__device__ __forceinline__ uint32_t smem_u32(const void* p) {
    uint32_t a;
    asm("{ .reg .u64 t; cvta.to.shared.u64 t, %1; cvt.u32.u64 %0, t; }"
        : "=r"(a) : "l"(p));
    return a;
}
__device__ __forceinline__ void cp16(uint32_t d, const void* s) {
    asm volatile("cp.async.cg.shared.global [%0], [%1], 16;" :: "r"(d), "l"(s));
}
__device__ __forceinline__ void cp_commit() {
    asm volatile("cp.async.commit_group;" ::: "memory");
}
template <int N> __device__ __forceinline__ void cp_wait() {
    asm volatile("cp.async.wait_group %0;" :: "n"(N) : "memory");
}
__device__ __forceinline__ uint32_t lds32(uint32_t a) {
    uint32_t v;
    asm volatile("ld.shared.b32 %0, [%1];" : "=r"(v) : "r"(a));
    return v;
}
__device__ __forceinline__ void mma16816(float* c, const uint32_t* a, const uint32_t* b) {
    asm volatile("mma.sync.aligned.m16n8k16.row.col.f32.bf16.bf16.f32 "
                 "{%0,%1,%2,%3}, {%4,%5,%6,%7}, {%8,%9}, {%0,%1,%2,%3};"
                 : "+f"(c[0]), "+f"(c[1]), "+f"(c[2]), "+f"(c[3])
                 : "r"(a[0]), "r"(a[1]), "r"(a[2]), "r"(a[3]),
                   "r"(b[0]), "r"(b[1]));
}
__device__ __forceinline__ uint32_t pk(bf16 a, bf16 b) {
    __nv_bfloat162 t = __halves2bfloat162(a, b);
    return *reinterpret_cast<uint32_t*>(&t);
}

// SMEM: per stage 4 tiles (A_hi, A_lo, B_hi, B_lo), each 128 rows x 32 bf16,
// row stride 80B (conflict-free for 4B lane loads: gid*20+tig distinct mod 32).
#define TILEB   10240          // 128 * 80
#define STAGEB  (4 * TILEB)    // 40960
#define SMEM_GEMM (2 * STAGEB) // 81920

__device__ __forceinline__ void load_stage(uint32_t sd,
        const bf16* __restrict__ Ahi, const bf16* __restrict__ Alo,
        const bf16* __restrict__ Bhi, const bf16* __restrict__ Blo,
        int rowBase, int colBase, int kld, int kk, int tid) {
    #pragma unroll
    for (int i = 0; i < 2; i++) {
        int idx = tid + i * 256;          // 0..511
        int row = idx >> 2, ch = idx & 3; // 128 rows x 4 16B-chunks
        size_t ga = (size_t)(rowBase + row) * kld + kk + ch * 8;
        size_t gb = (size_t)(colBase + row) * kld + kk + ch * 8;
        uint32_t so = row * 80 + ch * 16;
        cp16(sd + so,             Ahi + ga);
        cp16(sd + TILEB + so,     Alo + ga);
        cp16(sd + 2 * TILEB + so, Bhi + gb);
        cp16(sd + 3 * TILEB + so, Blo + gb);
    }
}

// One BK=32 stage of 3-pass bf16 MMA, fragments via direct LDS per PTX tables.
// Warp tile 64x32 (warp_m in {0,1}, warp_n in {0..3}).
__device__ __forceinline__ void compute_stage(uint32_t sbase, int warp_m, int warp_n,
                                              int lane, float acc[4][4][4]) {
    int gid = lane >> 2, tig = lane & 3;
    #pragma unroll
    for (int ks = 0; ks < 2; ks++) {
        int kbyte = ks * 32 + tig * 4;           // element k = ks*16 + 2*tig
        uint32_t ah[4][4], al[4][4];
        #pragma unroll
        for (int mf = 0; mf < 4; mf++) {
            uint32_t ra = sbase + (warp_m * 64 + mf * 16 + gid) * 80 + kbyte;
            ah[mf][0] = lds32(ra);                     // (m=gid,   k=2t)
            ah[mf][1] = lds32(ra + 8 * 80);            // (m=gid+8, k=2t)
            ah[mf][2] = lds32(ra + 16);                // (m=gid,   k=2t+8)
            ah[mf][3] = lds32(ra + 8 * 80 + 16);       // (m=gid+8, k=2t+8)
            al[mf][0] = lds32(ra + TILEB);
            al[mf][1] = lds32(ra + TILEB + 8 * 80);
            al[mf][2] = lds32(ra + TILEB + 16);
            al[mf][3] = lds32(ra + TILEB + 8 * 80 + 16);
        }
        uint32_t bh[4][2], bl[4][2];
        #pragma unroll
        for (int nf = 0; nf < 4; nf++) {
            uint32_t rb = sbase + 2 * TILEB + (warp_n * 32 + nf * 8 + gid) * 80 + kbyte;
            bh[nf][0] = lds32(rb);                     // (n=gid, k=2t)
            bh[nf][1] = lds32(rb + 16);                // (n=gid, k=2t+8)
            bl[nf][0] = lds32(rb + TILEB);
            bl[nf][1] = lds32(rb + TILEB + 16);
        }
        #pragma unroll
        for (int mf = 0; mf < 4; mf++)
            #pragma unroll
            for (int nf = 0; nf < 4; nf++) {
                mma16816(acc[mf][nf], ah[mf], bh[nf]);   // hi*hi
                mma16816(acc[mf][nf], ah[mf], bl[nf]);   // hi*lo
                mma16816(acc[mf][nf], al[mf], bh[nf]);   // lo*hi
            }
    }
}

__device__ __forceinline__ void run_mainloop(uint32_t sb,
        const bf16* Ahi, const bf16* Alo, const bf16* Bhi, const bf16* Blo,
        int rowBase, int colBase, int kld, int nc, int tid, float acc[4][4][4]) {
    int lane = tid & 31, wid = tid >> 5;
    int warp_m = wid & 1, warp_n = wid >> 1;
    load_stage(sb, Ahi, Alo, Bhi, Blo, rowBase, colBase, kld, 0, tid);
    cp_commit();
    #pragma unroll 1
    for (int ck = 0; ck < nc; ck++) {
        if (ck + 1 < nc) {
            load_stage(sb + ((ck + 1) & 1) * STAGEB, Ahi, Alo, Bhi, Blo,
                       rowBase, colBase, kld, (ck + 1) * 32, tid);
            cp_commit();
            cp_wait<1>();
        } else {
            cp_wait<0>();
        }
        __syncthreads();
        compute_stage(sb + (ck & 1) * STAGEB, warp_m, warp_n, lane, acc);
        __syncthreads();
    }
}

// ---------------------------------------------------------------------------
// Prologue kernels
// ---------------------------------------------------------------------------
__global__ void split_x(const float* __restrict__ x) {
    size_t i = (size_t)blockIdx.x * 256 + threadIdx.x;   // over NT*D/4
    float4 v = ((const float4*)x)[i];
    bf16 h0 = __float2bfloat16(v.x), h1 = __float2bfloat16(v.y);
    bf16 h2 = __float2bfloat16(v.z), h3 = __float2bfloat16(v.w);
    bf16 l0 = __float2bfloat16(v.x - __bfloat162float(h0));
    bf16 l1 = __float2bfloat16(v.y - __bfloat162float(h1));
    bf16 l2 = __float2bfloat16(v.z - __bfloat162float(h2));
    bf16 l3 = __float2bfloat16(v.w - __bfloat162float(h3));
    uint2 ph; ph.x = pk(h0, h1); ph.y = pk(h2, h3);
    uint2 pl; pl.x = pk(l0, l1); pl.y = pk(l2, l3);
    *(uint2*)&g_xhi[i * 4] = ph;
    *(uint2*)&g_xlo[i * 4] = pl;
}

// Transpose + split + permute weights: dst[perm(n)][koff + k] = split(W[k][n]).
// FIX (R5 post-mortem): destination arrays selected in DEVICE code via `which`.
// Previously g_WsThi/... were passed as kernel args from host — that takes the
// HOST shadow-symbol address, and on GB300 (ATS/pageableMemoryAccess=1) the GPU
// silently writes to host memory, leaving the device arrays zero.
__global__ void tp_split(const float* __restrict__ W, int which, int koff) {
    __shared__ float tile[32][33];
    int n0 = blockIdx.x * 32, k0 = blockIdx.y * 32;
    for (int r = threadIdx.y; r < 32; r += 8)
        tile[r][threadIdx.x] = W[(size_t)(k0 + r) * FH + n0 + threadIdx.x];
    __syncthreads();
    bf16* hiT = (which == 0) ? g_WsThi : g_WxThi;
    bf16* loT = (which == 0) ? g_WsTlo : g_WxTlo;
    int ldk   = (which == 0) ? 2048 : 1024;
    for (int r = threadIdx.y; r < 32; r += 8) {
        float v = tile[threadIdx.x][r];     // = W[k0+tx][n0+r]
        int p = perm(n0 + r);
        size_t o = (size_t)p * ldk + koff + k0 + threadIdx.x;
        bf16 h = __float2bfloat16(v);
        hiT[o] = h;
        loT[o] = __float2bfloat16(v - __bfloat162float(h));
    }
}

__global__ void bias_perm(const float* __restrict__ b) {
    int i = blockIdx.x * 256 + threadIdx.x;
    if (i < FH) g_bperm[perm(i)] = b[i];
}

// h0 = c0 = mean of 16 spatial values; seed bf16 A-operand buffer 0 (h half)
__global__ void init_hc(const float* __restrict__ A) {
    int idx = blockIdx.x * blockDim.x + threadIdx.x;
    if (idx >= NB * HH) return;
    const float4* p = (const float4*)(A + (size_t)idx * 16);
    float4 a = p[0], b = p[1], c = p[2], d = p[3];
    float s = (a.x + a.y + a.z + a.w) + (b.x + b.y + b.z + b.w)
            + (c.x + c.y + c.z + c.w) + (d.x + d.y + d.z + d.w);
    s *= (1.0f / 16.0f);
    g_h[idx] = s;
    g_c[idx] = s;
    int n = idx >> 10, j = idx & 1023;
    bf16 hb = __float2bfloat16(s);
    g_Ahi[0][n * 2048 + j] = hb;
    g_Alo[0][n * 2048 + j] = __float2bfloat16(s - __bfloat162float(hb));
}

// ---------------------------------------------------------------------------
// GEMM 1: Xf = x @ Wx + b (permuted cols). M=16384, N=4096, K=1024.
// ---------------------------------------------------------------------------
__global__ __launch_bounds__(256, 1) void gemm_x_mma() {
    extern __shared__ __align__(128) char smem[];
    uint32_t sb = smem_u32(smem);
    int tid = threadIdx.x;
    int rowBase = blockIdx.y * 128, colBase = blockIdx.x * 128;
    float acc[4][4][4] = {};
    run_mainloop(sb, g_xhi, g_xlo, g_WxThi, g_WxTlo,
                 rowBase, colBase, DD, DD / 32, tid, acc);

    int lane = tid & 31, wid = tid >> 5;
    int warp_m = wid & 1, warp_n = wid >> 1;
    #pragma unroll
    for (int mf = 0; mf < 4; mf++) {
        int r0 = rowBase + warp_m * 64 + mf * 16 + (lane >> 2);
        #pragma unroll
        for (int nf = 0; nf < 4; nf++) {
            int c = colBase + warp_n * 32 + nf * 8 + (lane & 3) * 2;
            float2 bb = *(const float2*)&g_bperm[c];
            float2 v0, v1;
            v0.x = acc[mf][nf][0] + bb.x; v0.y = acc[mf][nf][1] + bb.y;
            v1.x = acc[mf][nf][2] + bb.x; v1.y = acc[mf][nf][3] + bb.y;
            *(float2*)&g_Xf[(size_t)r0 * FH + c] = v0;
            *(float2*)&g_Xf[(size_t)(r0 + 8) * FH + c] = v1;
        }
    }
}

// ---------------------------------------------------------------------------
// GEMM 2 + fused gates. Reads A-operand buf[t&1], writes h for t+1 into buf[(t+1)&1].
// M=512, N=4096 (permuted), K=2048. Each 128-col tile holds i/f/o/g for 32 j's.
// ---------------------------------------------------------------------------
__global__ __launch_bounds__(256, 1) void gemm_step_mma(float* __restrict__ out, int t) {
    extern __shared__ __align__(128) char smem[];
    uint32_t sb = smem_u32(smem);
    float* vbuf = (float*)smem;                 // reuse after mainloop; stride 132
    int tid = threadIdx.x;
    int rowBase = blockIdx.y * 128, colBase = blockIdx.x * 128;
    int cur = t & 1, nxt = cur ^ 1;
    float acc[4][4][4] = {};
    run_mainloop(sb, g_Ahi[cur], g_Alo[cur], g_WsThi, g_WsTlo,
                 rowBase, colBase, 2048, 2048 / 32, tid, acc);

    int lane = tid & 31, wid = tid >> 5;
    int warp_m = wid & 1, warp_n = wid >> 1;
    // accum + Xf -> vbuf
    #pragma unroll
    for (int mf = 0; mf < 4; mf++) {
        int r = warp_m * 64 + mf * 16 + (lane >> 2);
        #pragma unroll
        for (int nf = 0; nf < 4; nf++) {
            int c = warp_n * 32 + nf * 8 + (lane & 3) * 2;
            size_t x0 = ((size_t)(rowBase + r) * TT + t) * FH + colBase + c;
            size_t x1 = ((size_t)(rowBase + r + 8) * TT + t) * FH + colBase + c;
            float2 xa = *(const float2*)&g_Xf[x0];
            float2 xb = *(const float2*)&g_Xf[x1];
            vbuf[r * 132 + c]           = acc[mf][nf][0] + xa.x;
            vbuf[r * 132 + c + 1]       = acc[mf][nf][1] + xa.y;
            vbuf[(r + 8) * 132 + c]     = acc[mf][nf][2] + xb.x;
            vbuf[(r + 8) * 132 + c + 1] = acc[mf][nf][3] + xb.y;
        }
    }
    __syncthreads();
    // gates: tile col layout [i(0:32) | f(32:64) | o(64:96) | g(96:128)] for j tile
    #pragma unroll 1
    for (int i = tid; i < 128 * 32; i += 256) {
        int r = i >> 5, jj = i & 31;
        float vi = vbuf[r * 132 + jj];
        float vf = vbuf[r * 132 + 32 + jj];
        float vo = vbuf[r * 132 + 64 + jj];
        float vg = vbuf[r * 132 + 96 + jj];
        float si = 1.0f / (1.0f + expf(-vi));
        float sf = 1.0f / (1.0f + expf(-vf));
        float so = 1.0f / (1.0f + expf(-vo));
        float tg = tanhf(vg);
        int n = rowBase + r;
        int j = (colBase >> 2) + jj;        // colBase/128 * 32
        int ci = n * HH + j;
        float cc = sf * g_c[ci] + si * tg;
        float hh = so * tanhf(cc);
        g_c[ci] = cc;
        g_h[ci] = hh;
        bf16 hb = __float2bfloat16(hh);
        g_Ahi[nxt][n * 2048 + j] = hb;
        g_Alo[nxt][n * 2048 + j] = __float2bfloat16(hh - __bfloat162float(hb));
        out[((size_t)n * TT + t) * HH + j] = hh;
    }
}

// ---------------------------------------------------------------------------
// Attention: writes bf16 split into A-operand buf[t&1], cols [1024, 2048)
// ---------------------------------------------------------------------------
__global__ __launch_bounds__(256) void attention(const float* __restrict__ A, int t) {
    int n = blockIdx.x;
    int cur = t & 1;
    const float* Afn = A + (size_t)n * (HH * 16);
    const float* hn  = g_h + (size_t)n * HH;

    float acc[16];
    #pragma unroll
    for (int k = 0; k < 16; k++) acc[k] = 0.0f;

    for (int hh = threadIdx.x; hh < HH; hh += 256) {
        float hv = hn[hh];
        const float4* row = (const float4*)(Afn + (size_t)hh * 16);
        float4 r0 = row[0], r1 = row[1], r2 = row[2], r3 = row[3];
        acc[0]  += hv * r0.x; acc[1]  += hv * r0.y; acc[2]  += hv * r0.z; acc[3]  += hv * r0.w;
        acc[4]  += hv * r1.x; acc[5]  += hv * r1.y; acc[6]  += hv * r1.z; acc[7]  += hv * r1.w;
        acc[8]  += hv * r2.x; acc[9]  += hv * r2.y; acc[10] += hv * r2.z; acc[11] += hv * r2.w;
        acc[12] += hv * r3.x; acc[13] += hv * r3.y; acc[14] += hv * r3.z; acc[15] += hv * r3.w;
    }
    #pragma unroll
    for (int off = 16; off > 0; off >>= 1)
        #pragma unroll
        for (int k = 0; k < 16; k++)
            acc[k] += __shfl_xor_sync(0xffffffffu, acc[k], off);

    __shared__ float warpacc[8][16];
    __shared__ float Msm[16];
    int lane = threadIdx.x & 31, wid = threadIdx.x >> 5;
    if (lane == 0) {
        #pragma unroll
        for (int k = 0; k < 16; k++) warpacc[wid][k] = acc[k];
    }
    __syncthreads();
    if (threadIdx.x == 0) {
        float sc[16];
        #pragma unroll
        for (int k = 0; k < 16; k++) {
            float s = 0.0f;
            #pragma unroll
            for (int w = 0; w < 8; w++) s += warpacc[w][k];
            sc[k] = s * (1.0f / 32.0f);    // /sqrt(1024)
        }
        float mx = sc[0];
        #pragma unroll
        for (int k = 1; k < 16; k++) mx = fmaxf(mx, sc[k]);
        float sum = 0.0f;
        #pragma unroll
        for (int k = 0; k < 16; k++) { sc[k] = expf(sc[k] - mx); sum += sc[k]; }
        float inv = 1.0f / sum;
        #pragma unroll
        for (int k = 0; k < 16; k++) Msm[k] = sc[k] * inv;
    }
    __syncthreads();

    float m[16];
    #pragma unroll
    for (int k = 0; k < 16; k++) m[k] = Msm[k];
    for (int hh = threadIdx.x; hh < HH; hh += 256) {
        const float4* row = (const float4*)(Afn + (size_t)hh * 16);
        float4 r0 = row[0], r1 = row[1], r2 = row[2], r3 = row[3];
        float s = r0.x*m[0] + r0.y*m[1] + r0.z*m[2] + r0.w*m[3]
                + r1.x*m[4] + r1.y*m[5] + r1.z*m[6] + r1.w*m[7]
                + r2.x*m[8] + r2.y*m[9] + r2.z*m[10] + r2.w*m[11]
                + r3.x*m[12] + r3.y*m[13] + r3.z*m[14] + r3.w*m[15];
        bf16 hb = __float2bfloat16(s);
        g_Ahi[cur][n * 2048 + 1024 + hh] = hb;
        g_Alo[cur][n * 2048 + 1024 + hh] = __float2bfloat16(s - __bfloat162float(hb));
    }
}

// ---------------------------------------------------------------------------
extern "C" void kernel_launch(void* const* d_in, const int* in_sizes, int n_in,
                              void* d_out, int out_size) {
    const float* x     = (const float*)d_in[0];
    const float* A     = (const float*)d_in[1];
    const float* Wx    = (const float*)d_in[2];
    const float* Wh    = (const float*)d_in[3];
    const float* Wattn = (const float*)d_in[4];
    const float* b     = (const float*)d_in[5];
    float* out = (float*)d_out;

    cudaFuncSetAttribute(gemm_x_mma,    cudaFuncAttributeMaxDynamicSharedMemorySize, SMEM_GEMM);
    cudaFuncSetAttribute(gemm_step_mma, cudaFuncAttributeMaxDynamicSharedMemorySize, SMEM_GEMM);

    split_x<<<(NB * TT * DD) / (256 * 4), 256>>>(x);
    tp_split<<<dim3(FH / 32, DD / 32), dim3(32, 8)>>>(Wh,    0, 0);
    tp_split<<<dim3(FH / 32, DD / 32), dim3(32, 8)>>>(Wattn, 0, 1024);
    tp_split<<<dim3(FH / 32, DD / 32), dim3(32, 8)>>>(Wx,    1, 0);
    bias_perm<<<FH / 256, 256>>>(b);
    init_hc<<<(NB * HH) / 256, 256>>>(A);

    gemm_x_mma<<<dim3(FH / 128, (NB * TT) / 128), 256, SMEM_GEMM>>>();

    for (int t = 0; t < TT; t++) {
        attention<<<NB, 256>>>(A, t);
        gemm_step_mma<<<dim3(FH / 128, NB / 128), 256, SMEM_GEMM>>>(out, t);
    }
}

// round 7
// speedup vs baseline: 2.6818x; 1.0253x over previous
#include <cuda_runtime.h>
#include <cuda_bf16.h>
#include <math.h>
#include <stdint.h>

#define NB   512
#define TT   32
#define DD   1024
#define HH   1024
#define FH   4096

typedef __nv_bfloat16 bf16;

// ---------------------------------------------------------------------------
// Scratch (__device__ globals; allocation-free rule)
// ---------------------------------------------------------------------------
__device__ float g_Xf[(size_t)NB * TT * FH];          // x@Wx + b, permuted cols (256 MB)
__device__ float g_h[NB * HH];                        // fp32 h (for attention)
__device__ float g_c[NB * HH];
// Double-buffered MMA A-operand [h | attn]
__device__ bf16  g_Ahi[2][NB * 2048];
__device__ bf16  g_Alo[2][NB * 2048];
__device__ bf16  g_xhi[(size_t)NB * TT * DD];
__device__ bf16  g_xlo[(size_t)NB * TT * DD];
__device__ bf16  g_WsThi[(size_t)FH * 2048];          // [Wh;Wattn]^T, permuted rows
__device__ bf16  g_WsTlo[(size_t)FH * 2048];
__device__ bf16  g_WxThi[(size_t)FH * DD];            // Wx^T, permuted rows
__device__ bf16  g_WxTlo[(size_t)FH * DD];
__device__ float g_bperm[FH];

// Column permutation: orig col n = gate*1024 + j  ->  p = (j/32)*128 + gate*32 + j%32
__device__ __forceinline__ int perm(int n) {
    int gate = n >> 10, j = n & 1023;
    return ((j >> 5) << 7) + (gate << 5) + (j & 31);
}

// ---------------------------------------------------------------------------
// PTX helpers
// ---------------------------------------------------------------------------
__device__ __forceinline__ uint32_t smem_u32(const void* p) {
    uint32_t a;
    asm("{ .reg .u64 t; cvta.to.shared.u64 t, %1; cvt.u32.u64 %0, t; }"
        : "=r"(a) : "l"(p));
    return a;
}
__device__ __forceinline__ void cp16(uint32_t d, const void* s) {
    asm volatile("cp.async.cg.shared.global [%0], [%1], 16;" :: "r"(d), "l"(s));
}
__device__ __forceinline__ void cp_commit() {
    asm volatile("cp.async.commit_group;" ::: "memory");
}
template <int N> __device__ __forceinline__ void cp_wait() {
    asm volatile("cp.async.wait_group %0;" :: "n"(N) : "memory");
}
__device__ __forceinline__ void ldsm4(uint32_t* r, uint32_t a) {
    asm volatile("ldmatrix.sync.aligned.m8n8.x4.shared.b16 {%0,%1,%2,%3}, [%4];"
                 : "=r"(r[0]), "=r"(r[1]), "=r"(r[2]), "=r"(r[3]) : "r"(a));
}
__device__ __forceinline__ void mma16816(float* c, const uint32_t* a, const uint32_t* b) {
    asm volatile("mma.sync.aligned.m16n8k16.row.col.f32.bf16.bf16.f32 "
                 "{%0,%1,%2,%3}, {%4,%5,%6,%7}, {%8,%9}, {%0,%1,%2,%3};"
                 : "+f"(c[0]), "+f"(c[1]), "+f"(c[2]), "+f"(c[3])
                 : "r"(a[0]), "r"(a[1]), "r"(a[2]), "r"(a[3]),
                   "r"(b[0]), "r"(b[1]));
}
__device__ __forceinline__ uint32_t pk(bf16 a, bf16 b) {
    __nv_bfloat162 t = __halves2bfloat162(a, b);
    return *reinterpret_cast<uint32_t*>(&t);
}

// SMEM: per stage 4 tiles (A_hi, A_lo, B_hi, B_lo), each 128 rows x 32 bf16,
// row stride 80B (16B-aligned rows; 20-word stride => conflict-free ldmatrix:
// 16B blocks (20r mod 32)/4 = {0,5,2,7,4,1,6,3} all distinct). 3-stage pipeline.
#define TILEB   10240          // 128 * 80
#define STAGEB  (4 * TILEB)    // 40960
#define NSTAGE  3
#define SMEM_GEMM (NSTAGE * STAGEB)   // 122880

__device__ __forceinline__ void load_stage(uint32_t sd,
        const bf16* __restrict__ Ahi, const bf16* __restrict__ Alo,
        const bf16* __restrict__ Bhi, const bf16* __restrict__ Blo,
        int rowBase, int colBase, int kld, int kk, int tid) {
    #pragma unroll
    for (int i = 0; i < 2; i++) {
        int idx = tid + i * 256;          // 0..511
        int row = idx >> 2, ch = idx & 3; // 128 rows x 4 16B-chunks
        size_t ga = (size_t)(rowBase + row) * kld + kk + ch * 8;
        size_t gb = (size_t)(colBase + row) * kld + kk + ch * 8;
        uint32_t so = row * 80 + ch * 16;
        cp16(sd + so,             Ahi + ga);
        cp16(sd + TILEB + so,     Alo + ga);
        cp16(sd + 2 * TILEB + so, Bhi + gb);
        cp16(sd + 3 * TILEB + so, Blo + gb);
    }
}

// One BK=32 stage of 3-pass bf16 MMA, fragments via ldmatrix.x4.
// Warp tile 64x32 (warp_m in {0,1}, warp_n in {0..3}).
// A x4 matrices (quad 0..3): (m0-7,k0-7),(m8-15,k0-7),(m0-7,k8-15),(m8-15,k8-15)
//   -> regs a0..a3 exactly per mma.m16n8k16 A-fragment tables.
// B x4 over 16 n-rows: (n0-7,k0-7),(n0-7,k8-15),(n8-15,k0-7),(n8-15,k8-15);
//   nf even uses regs {0,1}, nf odd uses regs {2,3}.
__device__ __forceinline__ void compute_stage(uint32_t sbase, int warp_m, int warp_n,
                                              int lane, float acc[4][4][4]) {
    int quad = lane >> 3, l7 = lane & 7;
    #pragma unroll
    for (int ks = 0; ks < 2; ks++) {
        uint32_t ah[4][4], al[4][4];
        #pragma unroll
        for (int mf = 0; mf < 4; mf++) {
            int row  = warp_m * 64 + mf * 16 + l7 + ((quad & 1) << 3);
            int koff = ks * 32 + ((quad >> 1) << 4);
            uint32_t a = sbase + row * 80 + koff;
            ldsm4(ah[mf], a);
            ldsm4(al[mf], a + TILEB);
        }
        uint32_t bh[2][4], bl[2][4];
        #pragma unroll
        for (int nf2 = 0; nf2 < 2; nf2++) {
            int row  = warp_n * 32 + nf2 * 16 + ((quad >> 1) << 3) + l7;
            int koff = ks * 32 + ((quad & 1) << 4);
            uint32_t a = sbase + 2 * TILEB + row * 80 + koff;
            ldsm4(bh[nf2], a);
            ldsm4(bl[nf2], a + TILEB);
        }
        #pragma unroll
        for (int mf = 0; mf < 4; mf++)
            #pragma unroll
            for (int nf = 0; nf < 4; nf++) {
                uint32_t* bph = &bh[nf >> 1][(nf & 1) * 2];
                uint32_t* bpl = &bl[nf >> 1][(nf & 1) * 2];
                mma16816(acc[mf][nf], ah[mf], bph);   // hi*hi
                mma16816(acc[mf][nf], ah[mf], bpl);   // hi*lo
                mma16816(acc[mf][nf], al[mf], bph);   // lo*hi
            }
    }
}

__device__ __forceinline__ void run_mainloop(uint32_t sb,
        const bf16* Ahi, const bf16* Alo, const bf16* Bhi, const bf16* Blo,
        int rowBase, int colBase, int kld, int nc, int tid, float acc[4][4][4]) {
    int lane = tid & 31, wid = tid >> 5;
    int warp_m = wid & 1, warp_n = wid >> 1;
    // prologue: prefetch stages 0 and 1
    load_stage(sb, Ahi, Alo, Bhi, Blo, rowBase, colBase, kld, 0, tid);
    cp_commit();
    load_stage(sb + STAGEB, Ahi, Alo, Bhi, Blo, rowBase, colBase, kld, 32, tid);
    cp_commit();
    int bufc = 0;   // buffer of stage ck (cycles 0,1,2)
    #pragma unroll 1
    for (int ck = 0; ck < nc; ck++) {
        int bufl = bufc + 2; if (bufl >= NSTAGE) bufl -= NSTAGE;   // buffer for ck+2
        if (ck + 2 < nc) {
            // buffer bufl was computed at stage ck-1; trailing sync of that
            // iteration ordered all its reads before this write.
            load_stage(sb + bufl * STAGEB, Ahi, Alo, Bhi, Blo,
                       rowBase, colBase, kld, (ck + 2) * 32, tid);
            cp_commit();
            cp_wait<2>();
        } else if (ck + 1 < nc) {
            cp_wait<1>();
        } else {
            cp_wait<0>();
        }
        __syncthreads();
        compute_stage(sb + bufc * STAGEB, warp_m, warp_n, lane, acc);
        __syncthreads();
        if (++bufc == NSTAGE) bufc = 0;
    }
}

// ---------------------------------------------------------------------------
// Prologue kernels
// ---------------------------------------------------------------------------
__global__ void split_x(const float* __restrict__ x) {
    size_t i = (size_t)blockIdx.x * 256 + threadIdx.x;   // over NT*D/4
    float4 v = ((const float4*)x)[i];
    bf16 h0 = __float2bfloat16(v.x), h1 = __float2bfloat16(v.y);
    bf16 h2 = __float2bfloat16(v.z), h3 = __float2bfloat16(v.w);
    bf16 l0 = __float2bfloat16(v.x - __bfloat162float(h0));
    bf16 l1 = __float2bfloat16(v.y - __bfloat162float(h1));
    bf16 l2 = __float2bfloat16(v.z - __bfloat162float(h2));
    bf16 l3 = __float2bfloat16(v.w - __bfloat162float(h3));
    uint2 ph; ph.x = pk(h0, h1); ph.y = pk(h2, h3);
    uint2 pl; pl.x = pk(l0, l1); pl.y = pk(l2, l3);
    *(uint2*)&g_xhi[i * 4] = ph;
    *(uint2*)&g_xlo[i * 4] = pl;
}

// Transpose + split + permute weights: dst[perm(n)][koff + k] = split(W[k][n]).
// Destination arrays selected in DEVICE code (host-side &__device__ symbol is
// the host shadow address; GB300 ATS dereferences it silently -> zeros).
__global__ void tp_split(const float* __restrict__ W, int which, int koff) {
    __shared__ float tile[32][33];
    int n0 = blockIdx.x * 32, k0 = blockIdx.y * 32;
    for (int r = threadIdx.y; r < 32; r += 8)
        tile[r][threadIdx.x] = W[(size_t)(k0 + r) * FH + n0 + threadIdx.x];
    __syncthreads();
    bf16* hiT = (which == 0) ? g_WsThi : g_WxThi;
    bf16* loT = (which == 0) ? g_WsTlo : g_WxTlo;
    int ldk   = (which == 0) ? 2048 : 1024;
    for (int r = threadIdx.y; r < 32; r += 8) {
        float v = tile[threadIdx.x][r];     // = W[k0+tx][n0+r]
        int p = perm(n0 + r);
        size_t o = (size_t)p * ldk + koff + k0 + threadIdx.x;
        bf16 h = __float2bfloat16(v);
        hiT[o] = h;
        loT[o] = __float2bfloat16(v - __bfloat162float(h));
    }
}

__global__ void bias_perm(const float* __restrict__ b) {
    int i = blockIdx.x * 256 + threadIdx.x;
    if (i < FH) g_bperm[perm(i)] = b[i];
}

// h0 = c0 = mean of 16 spatial values; seed bf16 A-operand buffer 0 (h half)
__global__ void init_hc(const float* __restrict__ A) {
    int idx = blockIdx.x * blockDim.x + threadIdx.x;
    if (idx >= NB * HH) return;
    const float4* p = (const float4*)(A + (size_t)idx * 16);
    float4 a = p[0], b = p[1], c = p[2], d = p[3];
    float s = (a.x + a.y + a.z + a.w) + (b.x + b.y + b.z + b.w)
            + (c.x + c.y + c.z + c.w) + (d.x + d.y + d.z + d.w);
    s *= (1.0f / 16.0f);
    g_h[idx] = s;
    g_c[idx] = s;
    int n = idx >> 10, j = idx & 1023;
    bf16 hb = __float2bfloat16(s);
    g_Ahi[0][n * 2048 + j] = hb;
    g_Alo[0][n * 2048 + j] = __float2bfloat16(s - __bfloat162float(hb));
}

// ---------------------------------------------------------------------------
// GEMM 1: Xf = x @ Wx + b (permuted cols). M=16384, N=4096, K=1024.
// ---------------------------------------------------------------------------
__global__ __launch_bounds__(256, 1) void gemm_x_mma() {
    extern __shared__ __align__(128) char smem[];
    uint32_t sb = smem_u32(smem);
    int tid = threadIdx.x;
    int rowBase = blockIdx.y * 128, colBase = blockIdx.x * 128;
    float acc[4][4][4] = {};
    run_mainloop(sb, g_xhi, g_xlo, g_WxThi, g_WxTlo,
                 rowBase, colBase, DD, DD / 32, tid, acc);

    int lane = tid & 31, wid = tid >> 5;
    int warp_m = wid & 1, warp_n = wid >> 1;
    #pragma unroll
    for (int mf = 0; mf < 4; mf++) {
        int r0 = rowBase + warp_m * 64 + mf * 16 + (lane >> 2);
        #pragma unroll
        for (int nf = 0; nf < 4; nf++) {
            int c = colBase + warp_n * 32 + nf * 8 + (lane & 3) * 2;
            float2 bb = *(const float2*)&g_bperm[c];
            float2 v0, v1;
            v0.x = acc[mf][nf][0] + bb.x; v0.y = acc[mf][nf][1] + bb.y;
            v1.x = acc[mf][nf][2] + bb.x; v1.y = acc[mf][nf][3] + bb.y;
            *(float2*)&g_Xf[(size_t)r0 * FH + c] = v0;
            *(float2*)&g_Xf[(size_t)(r0 + 8) * FH + c] = v1;
        }
    }
}

// ---------------------------------------------------------------------------
// GEMM 2 + fused gates. Reads A-operand buf[t&1], writes h for t+1 into buf[(t+1)&1].
// M=512, N=4096 (permuted), K=2048. Each 128-col tile holds i/f/o/g for 32 j's.
// ---------------------------------------------------------------------------
__global__ __launch_bounds__(256, 1) void gemm_step_mma(float* __restrict__ out, int t) {
    extern __shared__ __align__(128) char smem[];
    uint32_t sb = smem_u32(smem);
    float* vbuf = (float*)smem;                 // reuse after mainloop; stride 132
    int tid = threadIdx.x;
    int rowBase = blockIdx.y * 128, colBase = blockIdx.x * 128;
    int cur = t & 1, nxt = cur ^ 1;
    float acc[4][4][4] = {};
    run_mainloop(sb, g_Ahi[cur], g_Alo[cur], g_WsThi, g_WsTlo,
                 rowBase, colBase, 2048, 2048 / 32, tid, acc);

    int lane = tid & 31, wid = tid >> 5;
    int warp_m = wid & 1, warp_n = wid >> 1;
    // accum + Xf -> vbuf
    #pragma unroll
    for (int mf = 0; mf < 4; mf++) {
        int r = warp_m * 64 + mf * 16 + (lane >> 2);
        #pragma unroll
        for (int nf = 0; nf < 4; nf++) {
            int c = warp_n * 32 + nf * 8 + (lane & 3) * 2;
            size_t x0 = ((size_t)(rowBase + r) * TT + t) * FH + colBase + c;
            size_t x1 = ((size_t)(rowBase + r + 8) * TT + t) * FH + colBase + c;
            float2 xa = *(const float2*)&g_Xf[x0];
            float2 xb = *(const float2*)&g_Xf[x1];
            vbuf[r * 132 + c]           = acc[mf][nf][0] + xa.x;
            vbuf[r * 132 + c + 1]       = acc[mf][nf][1] + xa.y;
            vbuf[(r + 8) * 132 + c]     = acc[mf][nf][2] + xb.x;
            vbuf[(r + 8) * 132 + c + 1] = acc[mf][nf][3] + xb.y;
        }
    }
    __syncthreads();
    // gates: tile col layout [i(0:32) | f(32:64) | o(64:96) | g(96:128)] for j tile
    #pragma unroll 1
    for (int i = tid; i < 128 * 32; i += 256) {
        int r = i >> 5, jj = i & 31;
        float vi = vbuf[r * 132 + jj];
        float vf = vbuf[r * 132 + 32 + jj];
        float vo = vbuf[r * 132 + 64 + jj];
        float vg = vbuf[r * 132 + 96 + jj];
        float si = 1.0f / (1.0f + expf(-vi));
        float sf = 1.0f / (1.0f + expf(-vf));
        float so = 1.0f / (1.0f + expf(-vo));
        float tg = tanhf(vg);
        int n = rowBase + r;
        int j = (colBase >> 2) + jj;        // colBase/128 * 32
        int ci = n * HH + j;
        float cc = sf * g_c[ci] + si * tg;
        float hh = so * tanhf(cc);
        g_c[ci] = cc;
        g_h[ci] = hh;
        bf16 hb = __float2bfloat16(hh);
        g_Ahi[nxt][n * 2048 + j] = hb;
        g_Alo[nxt][n * 2048 + j] = __float2bfloat16(hh - __bfloat162float(hb));
        out[((size_t)n * TT + t) * HH + j] = hh;
    }
}

// ---------------------------------------------------------------------------
// Attention: writes bf16 split into A-operand buf[t&1], cols [1024, 2048)
// ---------------------------------------------------------------------------
__global__ __launch_bounds__(256) void attention(const float* __restrict__ A, int t) {
    int n = blockIdx.x;
    int cur = t & 1;
    const float* Afn = A + (size_t)n * (HH * 16);
    const float* hn  = g_h + (size_t)n * HH;

    float acc[16];
    #pragma unroll
    for (int k = 0; k < 16; k++) acc[k] = 0.0f;

    for (int hh = threadIdx.x; hh < HH; hh += 256) {
        float hv = hn[hh];
        const float4* row = (const float4*)(Afn + (size_t)hh * 16);
        float4 r0 = row[0], r1 = row[1], r2 = row[2], r3 = row[3];
        acc[0]  += hv * r0.x; acc[1]  += hv * r0.y; acc[2]  += hv * r0.z; acc[3]  += hv * r0.w;
        acc[4]  += hv * r1.x; acc[5]  += hv * r1.y; acc[6]  += hv * r1.z; acc[7]  += hv * r1.w;
        acc[8]  += hv * r2.x; acc[9]  += hv * r2.y; acc[10] += hv * r2.z; acc[11] += hv * r2.w;
        acc[12] += hv * r3.x; acc[13] += hv * r3.y; acc[14] += hv * r3.z; acc[15] += hv * r3.w;
    }
    #pragma unroll
    for (int off = 16; off > 0; off >>= 1)
        #pragma unroll
        for (int k = 0; k < 16; k++)
            acc[k] += __shfl_xor_sync(0xffffffffu, acc[k], off);

    __shared__ float warpacc[8][16];
    __shared__ float Msm[16];
    int lane = threadIdx.x & 31, wid = threadIdx.x >> 5;
    if (lane == 0) {
        #pragma unroll
        for (int k = 0; k < 16; k++) warpacc[wid][k] = acc[k];
    }
    __syncthreads();
    if (threadIdx.x == 0) {
        float sc[16];
        #pragma unroll
        for (int k = 0; k < 16; k++) {
            float s = 0.0f;
            #pragma unroll
            for (int w = 0; w < 8; w++) s += warpacc[w][k];
            sc[k] = s * (1.0f / 32.0f);    // /sqrt(1024)
        }
        float mx = sc[0];
        #pragma unroll
        for (int k = 1; k < 16; k++) mx = fmaxf(mx, sc[k]);
        float sum = 0.0f;
        #pragma unroll
        for (int k = 0; k < 16; k++) { sc[k] = expf(sc[k] - mx); sum += sc[k]; }
        float inv = 1.0f / sum;
        #pragma unroll
        for (int k = 0; k < 16; k++) Msm[k] = sc[k] * inv;
    }
    __syncthreads();

    float m[16];
    #pragma unroll
    for (int k = 0; k < 16; k++) m[k] = Msm[k];
    for (int hh = threadIdx.x; hh < HH; hh += 256) {
        const float4* row = (const float4*)(Afn + (size_t)hh * 16);
        float4 r0 = row[0], r1 = row[1], r2 = row[2], r3 = row[3];
        float s = r0.x*m[0] + r0.y*m[1] + r0.z*m[2] + r0.w*m[3]
                + r1.x*m[4] + r1.y*m[5] + r1.z*m[6] + r1.w*m[7]
                + r2.x*m[8] + r2.y*m[9] + r2.z*m[10] + r2.w*m[11]
                + r3.x*m[12] + r3.y*m[13] + r3.z*m[14] + r3.w*m[15];
        bf16 hb = __float2bfloat16(s);
        g_Ahi[cur][n * 2048 + 1024 + hh] = hb;
        g_Alo[cur][n * 2048 + 1024 + hh] = __float2bfloat16(s - __bfloat162float(hb));
    }
}

// ---------------------------------------------------------------------------
extern "C" void kernel_launch(void* const* d_in, const int* in_sizes, int n_in,
                              void* d_out, int out_size) {
    const float* x     = (const float*)d_in[0];
    const float* A     = (const float*)d_in[1];
    const float* Wx    = (const float*)d_in[2];
    const float* Wh    = (const float*)d_in[3];
    const float* Wattn = (const float*)d_in[4];
    const float* b     = (const float*)d_in[5];
    float* out = (float*)d_out;

    cudaFuncSetAttribute(gemm_x_mma,    cudaFuncAttributeMaxDynamicSharedMemorySize, SMEM_GEMM);
    cudaFuncSetAttribute(gemm_step_mma, cudaFuncAttributeMaxDynamicSharedMemorySize, SMEM_GEMM);

    split_x<<<(NB * TT * DD) / (256 * 4), 256>>>(x);
    tp_split<<<dim3(FH / 32, DD / 32), dim3(32, 8)>>>(Wh,    0, 0);
    tp_split<<<dim3(FH / 32, DD / 32), dim3(32, 8)>>>(Wattn, 0, 1024);
    tp_split<<<dim3(FH / 32, DD / 32), dim3(32, 8)>>>(Wx,    1, 0);
    bias_perm<<<FH / 256, 256>>>(b);
    init_hc<<<(NB * HH) / 256, 256>>>(A);

    gemm_x_mma<<<dim3(FH / 128, (NB * TT) / 128), 256, SMEM_GEMM>>>();

    for (int t = 0; t < TT; t++) {
        attention<<<NB, 256>>>(A, t);
        gemm_step_mma<<<dim3(FH / 128, NB / 128), 256, SMEM_GEMM>>>(out, t);
    }
}

// round 8
// speedup vs baseline: 5.7224x; 2.1338x over previous
#include <cuda_runtime.h>
#include <cuda_fp16.h>
#include <math.h>
#include <stdint.h>

#define NB   512
#define TT   32
#define DD   1024
#define HH   1024
#define FH   4096

// ---------------------------------------------------------------------------
// Scratch (__device__ globals; allocation-free rule)
// ---------------------------------------------------------------------------
__device__ float  g_Xf[(size_t)NB * TT * FH];        // x@Wx + b, permuted cols
__device__ float  g_h[NB * HH];                      // fp32 h (for attention)
__device__ float  g_c[NB * HH];
__device__ __half g_Af16[2][NB * 2048];              // [h | attn], double-buffered
__device__ __half g_xf16[(size_t)NB * TT * DD];
__device__ __half g_Wsf16[(size_t)FH * 2048];        // [Wh;Wattn]^T, permuted rows
__device__ __half g_Wxf16[(size_t)FH * DD];          // Wx^T, permuted rows
__device__ float  g_bperm[FH];

// Column permutation: orig col n = gate*1024 + j  ->  p = (j/32)*128 + gate*32 + j%32
__device__ __forceinline__ int perm(int n) {
    int gate = n >> 10, j = n & 1023;
    return ((j >> 5) << 7) + (gate << 5) + (j & 31);
}

// ---------------------------------------------------------------------------
// PTX helpers
// ---------------------------------------------------------------------------
__device__ __forceinline__ uint32_t smem_u32(const void* p) {
    uint32_t a;
    asm("{ .reg .u64 t; cvta.to.shared.u64 t, %1; cvt.u32.u64 %0, t; }"
        : "=r"(a) : "l"(p));
    return a;
}
__device__ __forceinline__ void cp16(uint32_t d, const void* s) {
    asm volatile("cp.async.cg.shared.global [%0], [%1], 16;" :: "r"(d), "l"(s));
}
__device__ __forceinline__ void cp_commit() {
    asm volatile("cp.async.commit_group;" ::: "memory");
}
template <int N> __device__ __forceinline__ void cp_wait() {
    asm volatile("cp.async.wait_group %0;" :: "n"(N) : "memory");
}
__device__ __forceinline__ void ldsm4(uint32_t* r, uint32_t a) {
    asm volatile("ldmatrix.sync.aligned.m8n8.x4.shared.b16 {%0,%1,%2,%3}, [%4];"
                 : "=r"(r[0]), "=r"(r[1]), "=r"(r[2]), "=r"(r[3]) : "r"(a));
}
__device__ __forceinline__ void mma16816(float* c, const uint32_t* a, const uint32_t* b) {
    asm volatile("mma.sync.aligned.m16n8k16.row.col.f32.f16.f16.f32 "
                 "{%0,%1,%2,%3}, {%4,%5,%6,%7}, {%8,%9}, {%0,%1,%2,%3};"
                 : "+f"(c[0]), "+f"(c[1]), "+f"(c[2]), "+f"(c[3])
                 : "r"(a[0]), "r"(a[1]), "r"(a[2]), "r"(a[3]),
                   "r"(b[0]), "r"(b[1]));
}

// SMEM: per stage 2 tiles (A, B), each 128 rows x 64 fp16 (128B data),
// row stride padded to 144B:
//  - ldmatrix phase (8 lanes, rows l7=0..7, fixed 16B col): word offsets
//    36*l7 mod 32 = 4*l7 -> 8 distinct 16B bank-groups, conflict-free.
//  - cp.async store (lanes 0-7 = one row, ch 0-7): contiguous 128B, clean.
#define ROWB    144
#define TILEB   (128 * ROWB)           // 18432
#define STAGEB  (2 * TILEB)            // 36864
#define NSTAGE  3
#define SMEM_GEMM (NSTAGE * STAGEB)    // 110592

__device__ __forceinline__ void load_stage(uint32_t sd,
        const __half* __restrict__ Aop, const __half* __restrict__ Bop,
        int rowBase, int colBase, int kld, int kk, int tid) {
    #pragma unroll
    for (int i = 0; i < 4; i++) {
        int idx = tid + i * 256;          // 0..1023
        int row = idx >> 3, ch = idx & 7; // 128 rows x 8 16B-chunks
        size_t ga = (size_t)(rowBase + row) * kld + kk + ch * 8;
        size_t gb = (size_t)(colBase + row) * kld + kk + ch * 8;
        uint32_t so = row * ROWB + ch * 16;
        cp16(sd + so,         Aop + ga);
        cp16(sd + TILEB + so, Bop + gb);
    }
}

// One BK=64 stage of single-pass fp16 MMA. Warp tile 64x32.
__device__ __forceinline__ void compute_stage(uint32_t sbase, int warp_m, int warp_n,
                                              int lane, float acc[4][4][4]) {
    int quad = lane >> 3, l7 = lane & 7;
    #pragma unroll
    for (int ks = 0; ks < 4; ks++) {
        uint32_t af[4][4];
        #pragma unroll
        for (int mf = 0; mf < 4; mf++) {
            int row  = warp_m * 64 + mf * 16 + l7 + ((quad & 1) << 3);
            int koff = ks * 32 + ((quad >> 1) << 4);
            ldsm4(af[mf], sbase + row * ROWB + koff);
        }
        uint32_t bf[2][4];
        #pragma unroll
        for (int nf2 = 0; nf2 < 2; nf2++) {
            int row  = warp_n * 32 + nf2 * 16 + ((quad >> 1) << 3) + l7;
            int koff = ks * 32 + ((quad & 1) << 4);
            ldsm4(bf[nf2], sbase + TILEB + row * ROWB + koff);
        }
        #pragma unroll
        for (int mf = 0; mf < 4; mf++)
            #pragma unroll
            for (int nf = 0; nf < 4; nf++)
                mma16816(acc[mf][nf], af[mf], &bf[nf >> 1][(nf & 1) * 2]);
    }
}

__device__ __forceinline__ void run_mainloop(uint32_t sb,
        const __half* Aop, const __half* Bop,
        int rowBase, int colBase, int kld, int nc, int tid, float acc[4][4][4]) {
    int lane = tid & 31, wid = tid >> 5;
    int warp_m = wid & 1, warp_n = wid >> 1;
    load_stage(sb, Aop, Bop, rowBase, colBase, kld, 0, tid);
    cp_commit();
    load_stage(sb + STAGEB, Aop, Bop, rowBase, colBase, kld, 64, tid);
    cp_commit();
    int bufc = 0;
    #pragma unroll 1
    for (int ck = 0; ck < nc; ck++) {
        int bufl = bufc + 2; if (bufl >= NSTAGE) bufl -= NSTAGE;
        if (ck + 2 < nc) {
            load_stage(sb + bufl * STAGEB, Aop, Bop,
                       rowBase, colBase, kld, (ck + 2) * 64, tid);
            cp_commit();
            cp_wait<2>();
        } else if (ck + 1 < nc) {
            cp_wait<1>();
        } else {
            cp_wait<0>();
        }
        __syncthreads();
        compute_stage(sb + bufc * STAGEB, warp_m, warp_n, lane, acc);
        __syncthreads();
        if (++bufc == NSTAGE) bufc = 0;
    }
}

// ---------------------------------------------------------------------------
// Prologue kernels
// ---------------------------------------------------------------------------
__global__ void split_x(const float* __restrict__ x) {
    size_t i = (size_t)blockIdx.x * 256 + threadIdx.x;   // over NT*D/4
    float4 v = ((const float4*)x)[i];
    __half2 p0 = __halves2half2(__float2half_rn(v.x), __float2half_rn(v.y));
    __half2 p1 = __halves2half2(__float2half_rn(v.z), __float2half_rn(v.w));
    uint2 o; o.x = *(uint32_t*)&p0; o.y = *(uint32_t*)&p1;
    *(uint2*)&g_xf16[i * 4] = o;
}

// Transpose + fp16 + permute weights: dst[perm(n)][koff + k] = (half)W[k][n].
// Destination arrays selected in DEVICE code (host-side &__device__ symbol is
// the host shadow address; GB300 ATS dereferences it silently -> zeros).
__global__ void tp_split(const float* __restrict__ W, int which, int koff) {
    __shared__ float tile[32][33];
    int n0 = blockIdx.x * 32, k0 = blockIdx.y * 32;
    for (int r = threadIdx.y; r < 32; r += 8)
        tile[r][threadIdx.x] = W[(size_t)(k0 + r) * FH + n0 + threadIdx.x];
    __syncthreads();
    __half* dst = (which == 0) ? g_Wsf16 : g_Wxf16;
    int ldk     = (which == 0) ? 2048 : 1024;
    for (int r = threadIdx.y; r < 32; r += 8) {
        float v = tile[threadIdx.x][r];     // = W[k0+tx][n0+r]
        int p = perm(n0 + r);
        dst[(size_t)p * ldk + koff + k0 + threadIdx.x] = __float2half_rn(v);
    }
}

__global__ void bias_perm(const float* __restrict__ b) {
    int i = blockIdx.x * 256 + threadIdx.x;
    if (i < FH) g_bperm[perm(i)] = b[i];
}

// h0 = c0 = mean of 16 spatial values; seed fp16 A-operand buffer 0 (h half)
__global__ void init_hc(const float* __restrict__ A) {
    int idx = blockIdx.x * blockDim.x + threadIdx.x;
    if (idx >= NB * HH) return;
    const float4* p = (const float4*)(A + (size_t)idx * 16);
    float4 a = p[0], b = p[1], c = p[2], d = p[3];
    float s = (a.x + a.y + a.z + a.w) + (b.x + b.y + b.z + b.w)
            + (c.x + c.y + c.z + c.w) + (d.x + d.y + d.z + d.w);
    s *= (1.0f / 16.0f);
    g_h[idx] = s;
    g_c[idx] = s;
    int n = idx >> 10, j = idx & 1023;
    g_Af16[0][n * 2048 + j] = __float2half_rn(s);
}

// ---------------------------------------------------------------------------
// GEMM 1: Xf = x @ Wx + b (permuted cols). M=16384, N=4096, K=1024.
// ---------------------------------------------------------------------------
__global__ __launch_bounds__(256, 1) void gemm_x_mma() {
    extern __shared__ __align__(128) char smem[];
    uint32_t sb = smem_u32(smem);
    int tid = threadIdx.x;
    int rowBase = blockIdx.y * 128, colBase = blockIdx.x * 128;
    float acc[4][4][4] = {};
    run_mainloop(sb, g_xf16, g_Wxf16, rowBase, colBase, DD, DD / 64, tid, acc);

    int lane = tid & 31, wid = tid >> 5;
    int warp_m = wid & 1, warp_n = wid >> 1;
    #pragma unroll
    for (int mf = 0; mf < 4; mf++) {
        int r0 = rowBase + warp_m * 64 + mf * 16 + (lane >> 2);
        #pragma unroll
        for (int nf = 0; nf < 4; nf++) {
            int c = colBase + warp_n * 32 + nf * 8 + (lane & 3) * 2;
            float2 bb = *(const float2*)&g_bperm[c];
            float2 v0, v1;
            v0.x = acc[mf][nf][0] + bb.x; v0.y = acc[mf][nf][1] + bb.y;
            v1.x = acc[mf][nf][2] + bb.x; v1.y = acc[mf][nf][3] + bb.y;
            *(float2*)&g_Xf[(size_t)r0 * FH + c] = v0;
            *(float2*)&g_Xf[(size_t)(r0 + 8) * FH + c] = v1;
        }
    }
}

// ---------------------------------------------------------------------------
// GEMM 2 + fused gates. Reads A-operand buf[t&1], writes h for t+1 into buf[(t+1)&1].
// M=512, N=4096 (permuted), K=2048. Each 128-col tile holds i/f/o/g for 32 j's.
// ---------------------------------------------------------------------------
__global__ __launch_bounds__(256, 1) void gemm_step_mma(float* __restrict__ out, int t) {
    extern __shared__ __align__(128) char smem[];
    uint32_t sb = smem_u32(smem);
    float* vbuf = (float*)smem;                 // reuse after mainloop; stride 132
    int tid = threadIdx.x;
    int rowBase = blockIdx.y * 128, colBase = blockIdx.x * 128;
    int cur = t & 1, nxt = cur ^ 1;
    float acc[4][4][4] = {};
    run_mainloop(sb, g_Af16[cur], g_Wsf16, rowBase, colBase, 2048, 2048 / 64, tid, acc);

    int lane = tid & 31, wid = tid >> 5;
    int warp_m = wid & 1, warp_n = wid >> 1;
    // accum + Xf -> vbuf
    #pragma unroll
    for (int mf = 0; mf < 4; mf++) {
        int r = warp_m * 64 + mf * 16 + (lane >> 2);
        #pragma unroll
        for (int nf = 0; nf < 4; nf++) {
            int c = warp_n * 32 + nf * 8 + (lane & 3) * 2;
            size_t x0 = ((size_t)(rowBase + r) * TT + t) * FH + colBase + c;
            size_t x1 = ((size_t)(rowBase + r + 8) * TT + t) * FH + colBase + c;
            float2 xa = *(const float2*)&g_Xf[x0];
            float2 xb = *(const float2*)&g_Xf[x1];
            vbuf[r * 132 + c]           = acc[mf][nf][0] + xa.x;
            vbuf[r * 132 + c + 1]       = acc[mf][nf][1] + xa.y;
            vbuf[(r + 8) * 132 + c]     = acc[mf][nf][2] + xb.x;
            vbuf[(r + 8) * 132 + c + 1] = acc[mf][nf][3] + xb.y;
        }
    }
    __syncthreads();
    // gates: tile col layout [i(0:32) | f(32:64) | o(64:96) | g(96:128)] for j tile
    #pragma unroll 1
    for (int i = tid; i < 128 * 32; i += 256) {
        int r = i >> 5, jj = i & 31;
        float vi = vbuf[r * 132 + jj];
        float vf = vbuf[r * 132 + 32 + jj];
        float vo = vbuf[r * 132 + 64 + jj];
        float vg = vbuf[r * 132 + 96 + jj];
        float si = 1.0f / (1.0f + expf(-vi));
        float sf = 1.0f / (1.0f + expf(-vf));
        float so = 1.0f / (1.0f + expf(-vo));
        float tg = tanhf(vg);
        int n = rowBase + r;
        int j = (colBase >> 2) + jj;        // colBase/128 * 32
        int ci = n * HH + j;
        float cc = sf * g_c[ci] + si * tg;
        float hh = so * tanhf(cc);
        g_c[ci] = cc;
        g_h[ci] = hh;
        g_Af16[nxt][n * 2048 + j] = __float2half_rn(hh);
        out[((size_t)n * TT + t) * HH + j] = hh;
    }
}

// ---------------------------------------------------------------------------
// Attention: writes fp16 into A-operand buf[t&1], cols [1024, 2048)
// ---------------------------------------------------------------------------
__global__ __launch_bounds__(256) void attention(const float* __restrict__ A, int t) {
    int n = blockIdx.x;
    int cur = t & 1;
    const float* Afn = A + (size_t)n * (HH * 16);
    const float* hn  = g_h + (size_t)n * HH;

    float acc[16];
    #pragma unroll
    for (int k = 0; k < 16; k++) acc[k] = 0.0f;

    for (int hh = threadIdx.x; hh < HH; hh += 256) {
        float hv = hn[hh];
        const float4* row = (const float4*)(Afn + (size_t)hh * 16);
        float4 r0 = row[0], r1 = row[1], r2 = row[2], r3 = row[3];
        acc[0]  += hv * r0.x; acc[1]  += hv * r0.y; acc[2]  += hv * r0.z; acc[3]  += hv * r0.w;
        acc[4]  += hv * r1.x; acc[5]  += hv * r1.y; acc[6]  += hv * r1.z; acc[7]  += hv * r1.w;
        acc[8]  += hv * r2.x; acc[9]  += hv * r2.y; acc[10] += hv * r2.z; acc[11] += hv * r2.w;
        acc[12] += hv * r3.x; acc[13] += hv * r3.y; acc[14] += hv * r3.z; acc[15] += hv * r3.w;
    }
    #pragma unroll
    for (int off = 16; off > 0; off >>= 1)
        #pragma unroll
        for (int k = 0; k < 16; k++)
            acc[k] += __shfl_xor_sync(0xffffffffu, acc[k], off);

    __shared__ float warpacc[8][16];
    __shared__ float Msm[16];
    int lane = threadIdx.x & 31, wid = threadIdx.x >> 5;
    if (lane == 0) {
        #pragma unroll
        for (int k = 0; k < 16; k++) warpacc[wid][k] = acc[k];
    }
    __syncthreads();
    if (threadIdx.x == 0) {
        float sc[16];
        #pragma unroll
        for (int k = 0; k < 16; k++) {
            float s = 0.0f;
            #pragma unroll
            for (int w = 0; w < 8; w++) s += warpacc[w][k];
            sc[k] = s * (1.0f / 32.0f);    // /sqrt(1024)
        }
        float mx = sc[0];
        #pragma unroll
        for (int k = 1; k < 16; k++) mx = fmaxf(mx, sc[k]);
        float sum = 0.0f;
        #pragma unroll
        for (int k = 0; k < 16; k++) { sc[k] = expf(sc[k] - mx); sum += sc[k]; }
        float inv = 1.0f / sum;
        #pragma unroll
        for (int k = 0; k < 16; k++) Msm[k] = sc[k] * inv;
    }
    __syncthreads();

    float m[16];
    #pragma unroll
    for (int k = 0; k < 16; k++) m[k] = Msm[k];
    for (int hh = threadIdx.x; hh < HH; hh += 256) {
        const float4* row = (const float4*)(Afn + (size_t)hh * 16);
        float4 r0 = row[0], r1 = row[1], r2 = row[2], r3 = row[3];
        float s = r0.x*m[0] + r0.y*m[1] + r0.z*m[2] + r0.w*m[3]
                + r1.x*m[4] + r1.y*m[5] + r1.z*m[6] + r1.w*m[7]
                + r2.x*m[8] + r2.y*m[9] + r2.z*m[10] + r2.w*m[11]
                + r3.x*m[12] + r3.y*m[13] + r3.z*m[14] + r3.w*m[15];
        g_Af16[cur][n * 2048 + 1024 + hh] = __float2half_rn(s);
    }
}

// ---------------------------------------------------------------------------
extern "C" void kernel_launch(void* const* d_in, const int* in_sizes, int n_in,
                              void* d_out, int out_size) {
    const float* x     = (const float*)d_in[0];
    const float* A     = (const float*)d_in[1];
    const float* Wx    = (const float*)d_in[2];
    const float* Wh    = (const float*)d_in[3];
    const float* Wattn = (const float*)d_in[4];
    const float* b     = (const float*)d_in[5];
    float* out = (float*)d_out;

    cudaFuncSetAttribute(gemm_x_mma,    cudaFuncAttributeMaxDynamicSharedMemorySize, SMEM_GEMM);
    cudaFuncSetAttribute(gemm_step_mma, cudaFuncAttributeMaxDynamicSharedMemorySize, SMEM_GEMM);

    split_x<<<(NB * TT * DD) / (256 * 4), 256>>>(x);
    tp_split<<<dim3(FH / 32, DD / 32), dim3(32, 8)>>>(Wh,    0, 0);
    tp_split<<<dim3(FH / 32, DD / 32), dim3(32, 8)>>>(Wattn, 0, 1024);
    tp_split<<<dim3(FH / 32, DD / 32), dim3(32, 8)>>>(Wx,    1, 0);
    bias_perm<<<FH / 256, 256>>>(b);
    init_hc<<<(NB * HH) / 256, 256>>>(A);

    gemm_x_mma<<<dim3(FH / 128, (NB * TT) / 128), 256, SMEM_GEMM>>>();

    for (int t = 0; t < TT; t++) {
        attention<<<NB, 256>>>(A, t);
        gemm_step_mma<<<dim3(FH / 128, NB / 128), 256, SMEM_GEMM>>>(out, t);
    }
}